// round 5
// baseline (speedup 1.0000x reference)
#include <cuda_runtime.h>
#include <cuda_bf16.h>
#include <cstdint>

// ---------------------------------------------------------------------------
// ChildSumTreeLSTM depth 17, D=H=128. R5: warp-level bf16 HMMA (mma.sync)
// with 3-pass hi/lo split for fp32 accuracy. tcgen05 unavailable at the
// harness's plain sm_103 PTX target.
// ---------------------------------------------------------------------------

#define DEPTH   17
#define HH      128
#define NNODES  ((1 << (DEPTH + 1)) - 1)        // 262143
#define NH      33554304L
#define PITCH   136                              // bf16 elems per smem row (+8 pad)

__device__ float g_X[4 * 33554304L];             // gate-major: i,f,o,u
__device__ float g_h[33554304L];
__device__ float g_c[33554304L];
// weight images: [mat][hi 2048 uint4 | lo 2048 uint4], dense [k][n] bf16
// mats: 0..3 = W_i,W_f,W_o,W_u ; 4..7 = U_i,U_f,U_o,U_u
__device__ uint4 g_Wb[8][4096];

__device__ __forceinline__ float sigf(float v)  { return 1.0f / (1.0f + __expf(-v)); }
__device__ __forceinline__ float tanhx(float v) {
    float r; asm("tanh.approx.f32 %0, %1;" : "=f"(r) : "f"(v)); return r;
}
__device__ __forceinline__ uint32_t smem_u32(const void* p) {
    uint32_t a; asm("{ .reg .u64 t; cvta.to.shared.u64 t, %1; cvt.u32.u64 %0, t; }"
                    : "=r"(a) : "l"(p)); return a;
}
__device__ __forceinline__ void ldsm4(uint32_t& r0, uint32_t& r1, uint32_t& r2,
                                      uint32_t& r3, uint32_t a) {
    asm volatile("ldmatrix.sync.aligned.m8n8.x4.shared.b16 {%0,%1,%2,%3}, [%4];"
                 : "=r"(r0), "=r"(r1), "=r"(r2), "=r"(r3) : "r"(a));
}
__device__ __forceinline__ void ldsm4t(uint32_t& r0, uint32_t& r1, uint32_t& r2,
                                       uint32_t& r3, uint32_t a) {
    asm volatile("ldmatrix.sync.aligned.m8n8.x4.trans.shared.b16 {%0,%1,%2,%3}, [%4];"
                 : "=r"(r0), "=r"(r1), "=r"(r2), "=r"(r3) : "r"(a));
}
__device__ __forceinline__ void mma16816(float* c, uint32_t a0, uint32_t a1,
                                         uint32_t a2, uint32_t a3,
                                         uint32_t b0, uint32_t b1) {
    asm volatile("mma.sync.aligned.m16n8k16.row.col.f32.bf16.bf16.f32 "
                 "{%0,%1,%2,%3}, {%4,%5,%6,%7}, {%8,%9}, {%0,%1,%2,%3};"
                 : "+f"(c[0]), "+f"(c[1]), "+f"(c[2]), "+f"(c[3])
                 : "r"(a0), "r"(a1), "r"(a2), "r"(a3), "r"(b0), "r"(b1));
}
// split two fp32 into bf16x2 hi + residual-lo words
__device__ __forceinline__ void split2(float a, float b, uint32_t& hi, uint32_t& lo) {
    __nv_bfloat162 h = __floats2bfloat162_rn(a, b);
    float ra = a - __bfloat162float(__low2bfloat16(h));
    float rb = b - __bfloat162float(__high2bfloat16(h));
    __nv_bfloat162 l = __floats2bfloat162_rn(ra, rb);
    hi = *(uint32_t*)&h; lo = *(uint32_t*)&l;
}

// ---------------------------------------------------------------------------
// Warp GEMM: dacc[16][4] = A(rows 16w..16w+15, 128k) @ B(128k x 128n),
// 3 split passes (hh, hl, lh). a_*/b_* are per-lane smem byte addresses.
// ---------------------------------------------------------------------------
__device__ __forceinline__ void wgemm3(float dacc[16][4],
                                       uint32_t a_hi, uint32_t a_lo,
                                       uint32_t b_hi, uint32_t b_lo)
{
#pragma unroll
    for (int nc = 0; nc < 16; ++nc)
        dacc[nc][0] = dacc[nc][1] = dacc[nc][2] = dacc[nc][3] = 0.f;
#pragma unroll
    for (int pass = 0; pass < 3; ++pass) {
        uint32_t ab = (pass == 2) ? a_lo : a_hi;
        uint32_t bb = (pass == 1) ? b_lo : b_hi;
#pragma unroll
        for (int kc = 0; kc < 8; ++kc) {
            uint32_t a0, a1, a2, a3;
            ldsm4(a0, a1, a2, a3, ab + kc * 32);
#pragma unroll
            for (int j = 0; j < 8; ++j) {
                uint32_t b0, b1, b2, b3;
                ldsm4t(b0, b1, b2, b3, bb + kc * (16 * PITCH * 2) + j * 32);
                mma16816(dacc[2 * j],     a0, a1, a2, a3, b0, b1);
                mma16816(dacc[2 * j + 1], a0, a1, a2, a3, b2, b3);
            }
        }
    }
}

// stage one weight image (hi+lo) from global into padded smem
__device__ __forceinline__ void stage_B(__nv_bfloat16* B_hi, __nv_bfloat16* B_lo,
                                        int mat, int tid)
{
    const uint4* src = g_Wb[mat];
    for (int i = tid; i < 2048; i += 256) {
        int row = i >> 4, ch = i & 15;
        *(uint4*)(B_hi + row * PITCH + ch * 8) = src[i];
        *(uint4*)(B_lo + row * PITCH + ch * 8) = src[i + 2048];
    }
}

// convert 128 fp32 rows (optionally summed pair) into A_hi/A_lo smem
// row r source = base + r*rstride (+ second row at +HH if SUM)
template<int SUM>
__device__ __forceinline__ void convert_A(__nv_bfloat16* A_hi, __nv_bfloat16* A_lo,
                                          const float* base, long rstride, int tid)
{
    int row = tid >> 1, half = (tid & 1) * 64;
    const float* s0 = base + (long)row * rstride + half;
#pragma unroll
    for (int i = 0; i < 16; ++i) {
        float4 v = *(const float4*)(s0 + i * 4);
        if (SUM) {
            float4 w = *(const float4*)(s0 + HH + i * 4);
            v.x += w.x; v.y += w.y; v.z += w.z; v.w += w.w;
        }
        uint32_t h0, l0, h1, l1;
        split2(v.x, v.y, h0, l0);
        split2(v.z, v.w, h1, l1);
        *(uint2*)(A_hi + row * PITCH + half + i * 4) = make_uint2(h0, h1);
        *(uint2*)(A_lo + row * PITCH + half + i * 4) = make_uint2(l0, l1);
    }
}

// ---------------------------------------------------------------------------
// Weight image builder: fp32 [k][n] -> bf16 hi/lo dense images.
// ---------------------------------------------------------------------------
__global__ void conv_w_kernel(
    const float* __restrict__ W_i, const float* __restrict__ W_f,
    const float* __restrict__ W_o, const float* __restrict__ W_u,
    const float* __restrict__ U_i, const float* __restrict__ U_f,
    const float* __restrict__ U_o, const float* __restrict__ U_u)
{
    const float* mats[8] = { W_i, W_f, W_o, W_u, U_i, U_f, U_o, U_u };
    const float* M = mats[blockIdx.x];
    __nv_bfloat16* hi = (__nv_bfloat16*)&g_Wb[blockIdx.x][0];
    __nv_bfloat16* lo = hi + 16384;
    for (int idx = threadIdx.x; idx < 16384; idx += blockDim.x) {
        float v = M[idx];
        __nv_bfloat16 h = __float2bfloat16(v);
        hi[idx] = h;
        lo[idx] = __float2bfloat16(v - __bfloat162float(h));
    }
}

// ---------------------------------------------------------------------------
// Input GEMM: X_g = x @ W_g + b_g. Block = 128 nodes, 4 gates sequential.
// smem: A_hi/A_lo/B_hi/B_lo, each 128 x PITCH bf16 = 139264 B total.
// ---------------------------------------------------------------------------
__global__ void __launch_bounds__(256) gx_kernel(
    const float* __restrict__ x,
    const float* __restrict__ b_i, const float* __restrict__ b_f,
    const float* __restrict__ b_o, const float* __restrict__ b_u)
{
    extern __shared__ __align__(16) __nv_bfloat16 sm[];
    __nv_bfloat16* A_hi = sm;
    __nv_bfloat16* A_lo = A_hi + 128 * PITCH;
    __nv_bfloat16* B_hi = A_lo + 128 * PITCH;
    __nv_bfloat16* B_lo = B_hi + 128 * PITCH;

    const int tid = threadIdx.x;
    const int w = tid >> 5, l = tid & 31;
    const int lr = l & 15, lc = l >> 4;
    const int qr = l >> 2, qc = (l & 3) * 2;
    const long r0 = (long)blockIdx.x * 128;

    // A conversion with row clamp (only last block's row 127 is OOB)
    {
        int row = tid >> 1, half = (tid & 1) * 64;
        long node = r0 + row; if (node >= NNODES) node = NNODES - 1;
        const float* s0 = x + node * HH + half;
#pragma unroll
        for (int i = 0; i < 16; ++i) {
            float4 v = *(const float4*)(s0 + i * 4);
            uint32_t h0, l0, h1, l1;
            split2(v.x, v.y, h0, l0);
            split2(v.z, v.w, h1, l1);
            *(uint2*)(A_hi + row * PITCH + half + i * 4) = make_uint2(h0, h1);
            *(uint2*)(A_lo + row * PITCH + half + i * 4) = make_uint2(l0, l1);
        }
    }
    stage_B(B_hi, B_lo, 0, tid);

    const uint32_t a_off = (uint32_t)((16 * w + lr) * PITCH + lc * 8) * 2;
    const uint32_t b_off = (uint32_t)(lr * PITCH + lc * 8) * 2;
    const uint32_t aH = smem_u32(A_hi) + a_off, aL = smem_u32(A_lo) + a_off;
    const uint32_t bH = smem_u32(B_hi) + b_off, bL = smem_u32(B_lo) + b_off;

    const float* Bv[4] = { b_i, b_f, b_o, b_u };
    const long row_a = r0 + 16 * w + qr;       // fragment row (c0,c1)
    const long row_b = row_a + 8;              // fragment row (c2,c3)

    for (int g = 0; g < 4; ++g) {
        __syncthreads();
        float dacc[16][4];
        wgemm3(dacc, aH, aL, bH, bL);
        __syncthreads();
        if (g < 3) stage_B(B_hi, B_lo, g + 1, tid);

        const float* bias = Bv[g];
        float* out = g_X + (long)g * NH;
#pragma unroll
        for (int nc = 0; nc < 16; ++nc) {
            int c = nc * 8 + qc;
            float2 bb = *(const float2*)(bias + c);
            if (row_a < NNODES)
                *(float2*)(out + row_a * HH + c) =
                    make_float2(dacc[nc][0] + bb.x, dacc[nc][1] + bb.y);
            if (row_b < NNODES)
                *(float2*)(out + row_b * HH + c) =
                    make_float2(dacc[nc][2] + bb.x, dacc[nc][3] + bb.y);
        }
    }
}

// ---------------------------------------------------------------------------
// Leaves.
// ---------------------------------------------------------------------------
__global__ void leaf_kernel()
{
    const long base = ((1L << DEPTH) - 1) * HH;
    long e = base + ((long)blockIdx.x * blockDim.x + threadIdx.x) * 4;
    float4 xi = *(const float4*)(g_X + e);
    float4 xo = *(const float4*)(g_X + 2 * NH + e);
    float4 xu = *(const float4*)(g_X + 3 * NH + e);
    float4 cv, hv;
    cv.x = sigf(xi.x) * tanhx(xu.x); hv.x = sigf(xo.x) * tanhx(cv.x);
    cv.y = sigf(xi.y) * tanhx(xu.y); hv.y = sigf(xo.y) * tanhx(cv.y);
    cv.z = sigf(xi.z) * tanhx(xu.z); hv.z = sigf(xo.z) * tanhx(cv.z);
    cv.w = sigf(xi.w) * tanhx(xu.w); hv.w = sigf(xo.w) * tanhx(cv.w);
    *(float4*)(g_c + e) = cv;
    *(float4*)(g_h + e) = hv;
}

// ---------------------------------------------------------------------------
// Tensor level kernel: 128 parents/block. Gemms: u,i (A=h~), f0 (A=c0),
// f1 (A=c1), o (A=h~ rebuilt). cc = running cell accumulator in fragments.
// ---------------------------------------------------------------------------
__global__ void __launch_bounds__(256) tlevel_kernel(int sl)
{
    extern __shared__ __align__(16) __nv_bfloat16 sm[];
    __nv_bfloat16* A_hi = sm;
    __nv_bfloat16* A_lo = A_hi + 128 * PITCH;
    __nv_bfloat16* B_hi = A_lo + 128 * PITCH;
    __nv_bfloat16* B_lo = B_hi + 128 * PITCH;

    const int tid = threadIdx.x;
    const int w = tid >> 5, l = tid & 31;
    const int lr = l & 15, lc = l >> 4;
    const int qr = l >> 2, qc = (l & 3) * 2;
    const long p0 = (long)blockIdx.x * 128;
    const long np = (long)sl + p0;              // first parent node of block
    const long cb = 2 * np + 1;                 // first child row

    const uint32_t a_off = (uint32_t)((16 * w + lr) * PITCH + lc * 8) * 2;
    const uint32_t b_off = (uint32_t)(lr * PITCH + lc * 8) * 2;
    const uint32_t aH = smem_u32(A_hi) + a_off, aL = smem_u32(A_lo) + a_off;
    const uint32_t bH = smem_u32(B_hi) + b_off, bL = smem_u32(B_lo) + b_off;

    const long n0 = np + 16 * w + qr;           // fragment node rows
    const long n1 = n0 + 8;

    float cc[16][4];
    float dacc[16][4];

#define X2(G, NODE, C) (*(const float2*)(g_X + (long)(G) * NH + (NODE) * HH + (C)))

    // A = h~ ; B = U_u
    convert_A<1>(A_hi, A_lo, g_h + cb * HH, 2 * HH, tid);
    stage_B(B_hi, B_lo, 7, tid);
    __syncthreads();
    wgemm3(dacc, aH, aL, bH, bL);
    __syncthreads();
    stage_B(B_hi, B_lo, 4, tid);                // U_i
#pragma unroll
    for (int nc = 0; nc < 16; ++nc) {
        int c = nc * 8 + qc;
        float2 xa = X2(3, n0, c), xb = X2(3, n1, c);
        cc[nc][0] = tanhx(dacc[nc][0] + xa.x);
        cc[nc][1] = tanhx(dacc[nc][1] + xa.y);
        cc[nc][2] = tanhx(dacc[nc][2] + xb.x);
        cc[nc][3] = tanhx(dacc[nc][3] + xb.y);
    }
    __syncthreads();
    wgemm3(dacc, aH, aL, bH, bL);
    __syncthreads();
    convert_A<0>(A_hi, A_lo, g_h + cb * HH, 2 * HH, tid);   // A = child0
    stage_B(B_hi, B_lo, 5, tid);                // U_f
#pragma unroll
    for (int nc = 0; nc < 16; ++nc) {
        int c = nc * 8 + qc;
        float2 xa = X2(0, n0, c), xb = X2(0, n1, c);
        cc[nc][0] *= sigf(dacc[nc][0] + xa.x);
        cc[nc][1] *= sigf(dacc[nc][1] + xa.y);
        cc[nc][2] *= sigf(dacc[nc][2] + xb.x);
        cc[nc][3] *= sigf(dacc[nc][3] + xb.y);
    }
    __syncthreads();
    wgemm3(dacc, aH, aL, bH, bL);
    __syncthreads();
    convert_A<0>(A_hi, A_lo, g_h + (cb + 1) * HH, 2 * HH, tid);  // A = child1
#pragma unroll
    for (int nc = 0; nc < 16; ++nc) {
        int c = nc * 8 + qc;
        float2 xa = X2(1, n0, c), xb = X2(1, n1, c);
        float2 ca = *(const float2*)(g_c + (2 * n0 + 1) * HH + c);
        float2 cb2 = *(const float2*)(g_c + (2 * n1 + 1) * HH + c);
        cc[nc][0] += sigf(dacc[nc][0] + xa.x) * ca.x;
        cc[nc][1] += sigf(dacc[nc][1] + xa.y) * ca.y;
        cc[nc][2] += sigf(dacc[nc][2] + xb.x) * cb2.x;
        cc[nc][3] += sigf(dacc[nc][3] + xb.y) * cb2.y;
    }
    __syncthreads();
    wgemm3(dacc, aH, aL, bH, bL);
    __syncthreads();
    convert_A<1>(A_hi, A_lo, g_h + cb * HH, 2 * HH, tid);   // A = h~ again
    stage_B(B_hi, B_lo, 6, tid);                // U_o
#pragma unroll
    for (int nc = 0; nc < 16; ++nc) {
        int c = nc * 8 + qc;
        float2 xa = X2(1, n0, c), xb = X2(1, n1, c);
        float2 ca = *(const float2*)(g_c + (2 * n0 + 2) * HH + c);
        float2 cb2 = *(const float2*)(g_c + (2 * n1 + 2) * HH + c);
        cc[nc][0] += sigf(dacc[nc][0] + xa.x) * ca.x;
        cc[nc][1] += sigf(dacc[nc][1] + xa.y) * ca.y;
        cc[nc][2] += sigf(dacc[nc][2] + xb.x) * cb2.x;
        cc[nc][3] += sigf(dacc[nc][3] + xb.y) * cb2.y;
    }
    __syncthreads();
    wgemm3(dacc, aH, aL, bH, bL);
#pragma unroll
    for (int nc = 0; nc < 16; ++nc) {
        int c = nc * 8 + qc;
        float2 xa = X2(2, n0, c), xb = X2(2, n1, c);
        float h0 = sigf(dacc[nc][0] + xa.x) * tanhx(cc[nc][0]);
        float h1 = sigf(dacc[nc][1] + xa.y) * tanhx(cc[nc][1]);
        float h2 = sigf(dacc[nc][2] + xb.x) * tanhx(cc[nc][2]);
        float h3 = sigf(dacc[nc][3] + xb.y) * tanhx(cc[nc][3]);
        *(float2*)(g_c + n0 * HH + c) = make_float2(cc[nc][0], cc[nc][1]);
        *(float2*)(g_c + n1 * HH + c) = make_float2(cc[nc][2], cc[nc][3]);
        *(float2*)(g_h + n0 * HH + c) = make_float2(h0, h1);
        *(float2*)(g_h + n1 * HH + c) = make_float2(h2, h3);
    }
#undef X2
}

// ---------------------------------------------------------------------------
// Small levels (nl < 128): one parent per block, 512 threads, k-split matvecs.
// ---------------------------------------------------------------------------
__global__ void __launch_bounds__(512) small_level_kernel(
    int sl,
    const float* __restrict__ U_i, const float* __restrict__ U_f,
    const float* __restrict__ U_o, const float* __restrict__ U_u)
{
    __shared__ float hs[3 * 128];
    __shared__ float part[5][4][128];

    const int t = threadIdx.x;
    const long node = sl + blockIdx.x;
    const long ch0  = 2 * node + 1;

    if (t < 128) {
        float h0 = g_h[ch0 * HH + t];
        float h1 = g_h[(ch0 + 1) * HH + t];
        hs[128 + t] = h0; hs[256 + t] = h1; hs[t] = h0 + h1;
    }
    __syncthreads();

    const int col = t & 127;
    const int kb  = (t >> 7) * 32;
    const int ks  = t >> 7;

#define JOB(J, SOFF, U) { const float* s = hs + (SOFF) * 128; float av = 0.f;  \
        _Pragma("unroll 8")                                                    \
        for (int k = 0; k < 32; ++k) av += s[kb + k] * (U)[(kb + k) * HH + col]; \
        part[J][ks][col] = av; }
    JOB(0, 0, U_i)
    JOB(1, 0, U_o)
    JOB(2, 0, U_u)
    JOB(3, 1, U_f)
    JOB(4, 2, U_f)
#undef JOB
    __syncthreads();

    if (t < 128) {
        float yi  = part[0][0][t] + part[0][1][t] + part[0][2][t] + part[0][3][t];
        float yo  = part[1][0][t] + part[1][1][t] + part[1][2][t] + part[1][3][t];
        float yu  = part[2][0][t] + part[2][1][t] + part[2][2][t] + part[2][3][t];
        float yf0 = part[3][0][t] + part[3][1][t] + part[3][2][t] + part[3][3][t];
        float yf1 = part[4][0][t] + part[4][1][t] + part[4][2][t] + part[4][3][t];
        long e = node * HH + t;
        float xf = g_X[NH + e];
        float iv = sigf(g_X[e] + yi);
        float ov = sigf(g_X[2 * NH + e] + yo);
        float uv = tanhx(g_X[3 * NH + e] + yu);
        float c  = iv * uv + sigf(xf + yf0) * g_c[ch0 * HH + t]
                           + sigf(xf + yf1) * g_c[(ch0 + 1) * HH + t];
        g_c[e] = c;
        g_h[e] = ov * tanhx(c);
    }
}

__global__ void out_kernel(float* __restrict__ out)
{
    int t = threadIdx.x;
    out[t] = (t < 128) ? g_h[t] : g_c[t - 128];
}

// ---------------------------------------------------------------------------
extern "C" void kernel_launch(void* const* d_in, const int* in_sizes, int n_in,
                              void* d_out, int out_size)
{
    const float* x   = (const float*)d_in[0];
    const float* W_i = (const float*)d_in[1];
    const float* b_i = (const float*)d_in[2];
    const float* U_i = (const float*)d_in[3];
    const float* W_f = (const float*)d_in[4];
    const float* b_f = (const float*)d_in[5];
    const float* U_f = (const float*)d_in[6];
    const float* W_o = (const float*)d_in[7];
    const float* b_o = (const float*)d_in[8];
    const float* U_o = (const float*)d_in[9];
    const float* W_u = (const float*)d_in[10];
    const float* b_u = (const float*)d_in[11];
    const float* U_u = (const float*)d_in[12];

    const int SMEM = 4 * 128 * PITCH * 2;       // 139264 B
    cudaFuncSetAttribute(gx_kernel,     cudaFuncAttributeMaxDynamicSharedMemorySize, SMEM);
    cudaFuncSetAttribute(tlevel_kernel, cudaFuncAttributeMaxDynamicSharedMemorySize, SMEM);

    conv_w_kernel<<<8, 256>>>(W_i, W_f, W_o, W_u, U_i, U_f, U_o, U_u);

    gx_kernel<<<(NNODES + 127) / 128, 256, SMEM>>>(x, b_i, b_f, b_o, b_u);

    leaf_kernel<<<(1 << DEPTH) * HH / 4 / 256, 256>>>();

    for (int l = DEPTH - 1; l >= 0; --l) {
        int nl = 1 << l;
        int sl = nl - 1;
        if (nl >= 128)
            tlevel_kernel<<<nl / 128, 256, SMEM>>>(sl);
        else
            small_level_kernel<<<nl, 512>>>(sl, U_i, U_f, U_o, U_u);
    }

    out_kernel<<<1, 256>>>((float*)d_out);
}

// round 6
// speedup vs baseline: 1.5129x; 1.5129x over previous
#include <cuda_runtime.h>
#include <cuda_bf16.h>
#include <cstdint>

// ---------------------------------------------------------------------------
// ChildSumTreeLSTM depth 17, D=H=128. R6: no g_X — input projections x@W_g
// are computed inside the level/leaf kernels on the tensor pipe (bf16 HMMA,
// 3-pass hi/lo split). A operands: x direct-from-global fragments; children
// h0/h1 converted once per block. 512 threads/block.
// ---------------------------------------------------------------------------

#define DEPTH   17
#define HH      128
#define NNODES  ((1 << (DEPTH + 1)) - 1)        // 262143
#define PITCH   136
#define SLOT    (128 * PITCH)                    // elems per half-buffer

__device__ float g_h[33554304L];
__device__ float g_c[33554304L];
// weight images: [mat][hi 2048 uint4 | lo 2048 uint4], dense [k][n] bf16
// mats: 0..3 = W_i,W_f,W_o,W_u ; 4..7 = U_i,U_f,U_o,U_u
__device__ uint4 g_Wb[8][4096];

__device__ __forceinline__ float sigf(float v)  { return 1.0f / (1.0f + __expf(-v)); }
__device__ __forceinline__ float tanhx(float v) {
    float r; asm("tanh.approx.f32 %0, %1;" : "=f"(r) : "f"(v)); return r;
}
__device__ __forceinline__ uint32_t smem_u32(const void* p) {
    uint32_t a; asm("{ .reg .u64 t; cvta.to.shared.u64 t, %1; cvt.u32.u64 %0, t; }"
                    : "=r"(a) : "l"(p)); return a;
}
__device__ __forceinline__ void ldsm4(uint32_t& r0, uint32_t& r1, uint32_t& r2,
                                      uint32_t& r3, uint32_t a) {
    asm volatile("ldmatrix.sync.aligned.m8n8.x4.shared.b16 {%0,%1,%2,%3}, [%4];"
                 : "=r"(r0), "=r"(r1), "=r"(r2), "=r"(r3) : "r"(a));
}
__device__ __forceinline__ void ldsm4t(uint32_t& r0, uint32_t& r1, uint32_t& r2,
                                       uint32_t& r3, uint32_t a) {
    asm volatile("ldmatrix.sync.aligned.m8n8.x4.trans.shared.b16 {%0,%1,%2,%3}, [%4];"
                 : "=r"(r0), "=r"(r1), "=r"(r2), "=r"(r3) : "r"(a));
}
__device__ __forceinline__ void mma16816(float* c, uint32_t a0, uint32_t a1,
                                         uint32_t a2, uint32_t a3,
                                         uint32_t b0, uint32_t b1) {
    asm volatile("mma.sync.aligned.m16n8k16.row.col.f32.bf16.bf16.f32 "
                 "{%0,%1,%2,%3}, {%4,%5,%6,%7}, {%8,%9}, {%0,%1,%2,%3};"
                 : "+f"(c[0]), "+f"(c[1]), "+f"(c[2]), "+f"(c[3])
                 : "r"(a0), "r"(a1), "r"(a2), "r"(a3), "r"(b0), "r"(b1));
}
__device__ __forceinline__ void split2(float a, float b, uint32_t& hi, uint32_t& lo) {
    __nv_bfloat162 h = __floats2bfloat162_rn(a, b);
    float ra = a - __bfloat162float(__low2bfloat16(h));
    float rb = b - __bfloat162float(__high2bfloat16(h));
    __nv_bfloat162 l = __floats2bfloat162_rn(ra, rb);
    hi = *(uint32_t*)&h; lo = *(uint32_t*)&l;
}

// inner 3-pass block: given A frags (ah/al) for this kc, do B loads + 6 MMAs/j
#define INNER_J(DACC, BHP, BLP)                                                \
    _Pragma("unroll")                                                          \
    for (int j = 0; j < 4; ++j) {                                              \
        uint32_t bh0,bh1,bh2,bh3, bl0,bl1,bl2,bl3;                             \
        ldsm4t(bh0,bh1,bh2,bh3, (BHP) + j*32);                                 \
        ldsm4t(bl0,bl1,bl2,bl3, (BLP) + j*32);                                 \
        mma16816(DACC[2*j],   ah0,ah1,ah2,ah3, bh0,bh1);                       \
        mma16816(DACC[2*j+1], ah0,ah1,ah2,ah3, bh2,bh3);                       \
        mma16816(DACC[2*j],   ah0,ah1,ah2,ah3, bl0,bl1);                       \
        mma16816(DACC[2*j+1], ah0,ah1,ah2,ah3, bl2,bl3);                       \
        mma16816(DACC[2*j],   al0,al1,al2,al3, bh0,bh1);                       \
        mma16816(DACC[2*j+1], al0,al1,al2,al3, bh2,bh3);                       \
    }

// dacc += Asmem @ Bsmem   (A via ldmatrix, all 3 split passes fused)
__device__ __forceinline__ void gemm_S(float (*dacc)[4], uint32_t aH, uint32_t aL,
                                       uint32_t bH, uint32_t bL)
{
#pragma unroll
    for (int kc = 0; kc < 8; ++kc) {
        uint32_t ah0,ah1,ah2,ah3, al0,al1,al2,al3;
        ldsm4(ah0,ah1,ah2,ah3, aH + kc*32);
        ldsm4(al0,al1,al2,al3, aL + kc*32);
        uint32_t bhp = bH + kc*(16*PITCH*2), blp = bL + kc*(16*PITCH*2);
        INNER_J(dacc, bhp, blp)
    }
}

// dacc += Xglobal @ Bsmem  (A fragments loaded straight from fp32 global)
__device__ __forceinline__ void gemm_X(float (*dacc)[4],
                                       const float* __restrict__ xA,
                                       const float* __restrict__ xB,
                                       int qc2, uint32_t bH, uint32_t bL)
{
#pragma unroll
    for (int kc = 0; kc < 8; ++kc) {
        int k0 = kc*16 + qc2;
        float2 v0 = *(const float2*)(xA + k0);
        float2 v1 = *(const float2*)(xB + k0);
        float2 v2 = *(const float2*)(xA + k0 + 8);
        float2 v3 = *(const float2*)(xB + k0 + 8);
        uint32_t ah0,al0,ah1,al1,ah2,al2,ah3,al3;
        split2(v0.x,v0.y,ah0,al0); split2(v1.x,v1.y,ah1,al1);
        split2(v2.x,v2.y,ah2,al2); split2(v3.x,v3.y,ah3,al3);
        uint32_t bhp = bH + kc*(16*PITCH*2), blp = bL + kc*(16*PITCH*2);
        INNER_J(dacc, bhp, blp)
    }
}

__device__ __forceinline__ void stage_B(__nv_bfloat16* Bh, __nv_bfloat16* Bl,
                                        int mat, int tid, int nthr)
{
    const uint4* src = g_Wb[mat];
    for (int i = tid; i < 2048; i += nthr) {
        int row = i >> 4, ch = i & 15;
        *(uint4*)(Bh + row * PITCH + ch * 8) = src[i];
        *(uint4*)(Bl + row * PITCH + ch * 8) = src[i + 2048];
    }
}

// ---------------------------------------------------------------------------
__global__ void conv_w_kernel(
    const float* __restrict__ W_i, const float* __restrict__ W_f,
    const float* __restrict__ W_o, const float* __restrict__ W_u,
    const float* __restrict__ U_i, const float* __restrict__ U_f,
    const float* __restrict__ U_o, const float* __restrict__ U_u)
{
    const float* mats[8] = { W_i, W_f, W_o, W_u, U_i, U_f, U_o, U_u };
    const float* M = mats[blockIdx.x];
    __nv_bfloat16* hi = (__nv_bfloat16*)&g_Wb[blockIdx.x][0];
    __nv_bfloat16* lo = hi + 16384;
    for (int idx = threadIdx.x; idx < 16384; idx += blockDim.x) {
        float v = M[idx];
        __nv_bfloat16 h = __float2bfloat16(v);
        hi[idx] = h;
        lo[idx] = __float2bfloat16(v - __bfloat162float(h));
    }
}

#define ZERO(D) { _Pragma("unroll") for (int t = 0; t < 8; ++t) \
        { D[t][0]=0.f; D[t][1]=0.f; D[t][2]=0.f; D[t][3]=0.f; } }

// ---------------------------------------------------------------------------
// Leaf kernel: 128 leaves/block, gates u,i,o from x@W only; write h,c.
// smem: B hi/lo (69632 B).
// ---------------------------------------------------------------------------
__global__ void __launch_bounds__(512) leaf_kernel(
    const float* __restrict__ x,
    const float* __restrict__ b_i, const float* __restrict__ b_o,
    const float* __restrict__ b_u)
{
    extern __shared__ __align__(16) __nv_bfloat16 sm[];
    __nv_bfloat16* Bh = sm;
    __nv_bfloat16* Bl = sm + SLOT;

    const int tid = threadIdx.x;
    const int w = tid >> 5, l = tid & 31;
    const int mg = w >> 1, nh = w & 1;
    const int lr = l & 15, lc = l >> 4;
    const int qr = l >> 2, qc2 = (l & 3) * 2;

    const long n0 = (long)((1 << DEPTH) - 1) + (long)blockIdx.x * 128 + mg*16 + qr;
    const long n1 = n0 + 8;
    const float* xA = x + n0*HH;
    const float* xB = x + n1*HH;
    const int cbase = nh*64 + qc2;

    const uint32_t b_off = (uint32_t)(lr*PITCH + nh*64 + lc*8)*2;
    const uint32_t bH = smem_u32(Bh)+b_off, bL = smem_u32(Bl)+b_off;

    float dacc[8][4], cc[8][4];

    stage_B(Bh, Bl, 3, tid, 512);           // W_u
    __syncthreads();
    ZERO(dacc); gemm_X(dacc, xA, xB, qc2, bH, bL);
#pragma unroll
    for (int t = 0; t < 8; ++t) {
        float2 b = *(const float2*)(b_u + cbase + t*8);
        cc[t][0]=tanhx(dacc[t][0]+b.x); cc[t][1]=tanhx(dacc[t][1]+b.y);
        cc[t][2]=tanhx(dacc[t][2]+b.x); cc[t][3]=tanhx(dacc[t][3]+b.y);
    }
    __syncthreads(); stage_B(Bh, Bl, 0, tid, 512); __syncthreads();   // W_i
    ZERO(dacc); gemm_X(dacc, xA, xB, qc2, bH, bL);
#pragma unroll
    for (int t = 0; t < 8; ++t) {
        float2 b = *(const float2*)(b_i + cbase + t*8);
        cc[t][0]*=sigf(dacc[t][0]+b.x); cc[t][1]*=sigf(dacc[t][1]+b.y);
        cc[t][2]*=sigf(dacc[t][2]+b.x); cc[t][3]*=sigf(dacc[t][3]+b.y);
    }
    __syncthreads(); stage_B(Bh, Bl, 2, tid, 512); __syncthreads();   // W_o
    ZERO(dacc); gemm_X(dacc, xA, xB, qc2, bH, bL);
#pragma unroll
    for (int t = 0; t < 8; ++t) {
        int c = cbase + t*8;
        float2 b = *(const float2*)(b_o + c);
        float h0 = sigf(dacc[t][0]+b.x)*tanhx(cc[t][0]);
        float h1 = sigf(dacc[t][1]+b.y)*tanhx(cc[t][1]);
        float h2 = sigf(dacc[t][2]+b.x)*tanhx(cc[t][2]);
        float h3 = sigf(dacc[t][3]+b.y)*tanhx(cc[t][3]);
        *(float2*)(g_c + n0*HH + c) = make_float2(cc[t][0], cc[t][1]);
        *(float2*)(g_c + n1*HH + c) = make_float2(cc[t][2], cc[t][3]);
        *(float2*)(g_h + n0*HH + c) = make_float2(h0, h1);
        *(float2*)(g_h + n1*HH + c) = make_float2(h2, h3);
    }
}

// ---------------------------------------------------------------------------
// Tensor level kernel: 128 parents/block, 512 threads.
// Per gate g: dacc = x@W_g + h0@U_g + h1@U_g (u,i,o); f: Xf=x@W_f kept in
// regs, f0 = h0@U_f + Xf, f1 = h1@U_f + Xf.
// smem: S0,S1 (children bf16 hi/lo) + B stage = 208896 B.
// ---------------------------------------------------------------------------
__global__ void __launch_bounds__(512) tlevel_kernel(
    int sl, const float* __restrict__ x,
    const float* __restrict__ b_i, const float* __restrict__ b_f,
    const float* __restrict__ b_o, const float* __restrict__ b_u)
{
    extern __shared__ __align__(16) __nv_bfloat16 sm[];
    __nv_bfloat16* S0h = sm;
    __nv_bfloat16* S0l = sm + SLOT;
    __nv_bfloat16* S1h = sm + 2*SLOT;
    __nv_bfloat16* S1l = sm + 3*SLOT;
    __nv_bfloat16* Bh  = sm + 4*SLOT;
    __nv_bfloat16* Bl  = sm + 5*SLOT;

    const int tid = threadIdx.x;
    const int w = tid >> 5, l = tid & 31;
    const int mg = w >> 1, nh = w & 1;
    const int lr = l & 15, lc = l >> 4;
    const int qr = l >> 2, qc2 = (l & 3) * 2;

    const long np = (long)sl + (long)blockIdx.x * 128;
    const long cb = 2*np + 1;

    // convert children h0 -> S0, h1 -> S1 (once per block)
    {
        int slot = tid >> 8;
        int row  = (tid & 255) >> 1;
        int half = (tid & 1) * 64;
        const float* src = g_h + (cb + 2*row + slot)*HH + half;
        __nv_bfloat16* dh = slot ? S1h : S0h;
        __nv_bfloat16* dl = slot ? S1l : S0l;
#pragma unroll
        for (int i = 0; i < 16; ++i) {
            float4 v = *(const float4*)(src + i*4);
            uint32_t h0,l0,h1,l1;
            split2(v.x,v.y,h0,l0); split2(v.z,v.w,h1,l1);
            *(uint2*)(dh + row*PITCH + half + i*4) = make_uint2(h0,h1);
            *(uint2*)(dl + row*PITCH + half + i*4) = make_uint2(l0,l1);
        }
    }
    stage_B(Bh, Bl, 3, tid, 512);           // W_u
    __syncthreads();

    const uint32_t a_off = (uint32_t)((16*mg + lr)*PITCH + lc*8)*2;
    const uint32_t b_off = (uint32_t)(lr*PITCH + nh*64 + lc*8)*2;
    const uint32_t s0H = smem_u32(S0h)+a_off, s0L = smem_u32(S0l)+a_off;
    const uint32_t s1H = smem_u32(S1h)+a_off, s1L = smem_u32(S1l)+a_off;
    const uint32_t bH = smem_u32(Bh)+b_off, bL = smem_u32(Bl)+b_off;

    const long n0 = np + mg*16 + qr, n1 = n0 + 8;
    const float* xA = x + n0*HH;
    const float* xB = x + n1*HH;
    const int cbase = nh*64 + qc2;

    float dacc[8][4], cc[8][4], xf[8][4];

#define RESTAGE(M) do { __syncthreads(); stage_B(Bh, Bl, M, tid, 512); \
        __syncthreads(); } while (0)

    // ---- u ----
    ZERO(dacc); gemm_X(dacc, xA, xB, qc2, bH, bL);
    RESTAGE(7);
    gemm_S(dacc, s0H, s0L, bH, bL); gemm_S(dacc, s1H, s1L, bH, bL);
#pragma unroll
    for (int t = 0; t < 8; ++t) {
        float2 b = *(const float2*)(b_u + cbase + t*8);
        cc[t][0]=tanhx(dacc[t][0]+b.x); cc[t][1]=tanhx(dacc[t][1]+b.y);
        cc[t][2]=tanhx(dacc[t][2]+b.x); cc[t][3]=tanhx(dacc[t][3]+b.y);
    }
    // ---- i ----
    RESTAGE(0);
    ZERO(dacc); gemm_X(dacc, xA, xB, qc2, bH, bL);
    RESTAGE(4);
    gemm_S(dacc, s0H, s0L, bH, bL); gemm_S(dacc, s1H, s1L, bH, bL);
#pragma unroll
    for (int t = 0; t < 8; ++t) {
        float2 b = *(const float2*)(b_i + cbase + t*8);
        cc[t][0]*=sigf(dacc[t][0]+b.x); cc[t][1]*=sigf(dacc[t][1]+b.y);
        cc[t][2]*=sigf(dacc[t][2]+b.x); cc[t][3]*=sigf(dacc[t][3]+b.y);
    }
    // ---- f: Xf = x@W_f + b_f ----
    RESTAGE(1);
    ZERO(dacc); gemm_X(dacc, xA, xB, qc2, bH, bL);
#pragma unroll
    for (int t = 0; t < 8; ++t) {
        float2 b = *(const float2*)(b_f + cbase + t*8);
        xf[t][0]=dacc[t][0]+b.x; xf[t][1]=dacc[t][1]+b.y;
        xf[t][2]=dacc[t][2]+b.x; xf[t][3]=dacc[t][3]+b.y;
    }
    RESTAGE(5);
    ZERO(dacc); gemm_S(dacc, s0H, s0L, bH, bL);
#pragma unroll
    for (int t = 0; t < 8; ++t) {
        int c = cbase + t*8;
        float2 ca = *(const float2*)(g_c + (2*n0+1)*HH + c);
        float2 cbv = *(const float2*)(g_c + (2*n1+1)*HH + c);
        cc[t][0]+=sigf(dacc[t][0]+xf[t][0])*ca.x;
        cc[t][1]+=sigf(dacc[t][1]+xf[t][1])*ca.y;
        cc[t][2]+=sigf(dacc[t][2]+xf[t][2])*cbv.x;
        cc[t][3]+=sigf(dacc[t][3]+xf[t][3])*cbv.y;
    }
    ZERO(dacc); gemm_S(dacc, s1H, s1L, bH, bL);
#pragma unroll
    for (int t = 0; t < 8; ++t) {
        int c = cbase + t*8;
        float2 ca = *(const float2*)(g_c + (2*n0+2)*HH + c);
        float2 cbv = *(const float2*)(g_c + (2*n1+2)*HH + c);
        cc[t][0]+=sigf(dacc[t][0]+xf[t][0])*ca.x;
        cc[t][1]+=sigf(dacc[t][1]+xf[t][1])*ca.y;
        cc[t][2]+=sigf(dacc[t][2]+xf[t][2])*cbv.x;
        cc[t][3]+=sigf(dacc[t][3]+xf[t][3])*cbv.y;
    }
    // ---- o + store ----
    RESTAGE(2);
    ZERO(dacc); gemm_X(dacc, xA, xB, qc2, bH, bL);
    RESTAGE(6);
    gemm_S(dacc, s0H, s0L, bH, bL); gemm_S(dacc, s1H, s1L, bH, bL);
#pragma unroll
    for (int t = 0; t < 8; ++t) {
        int c = cbase + t*8;
        float2 b = *(const float2*)(b_o + c);
        float h0 = sigf(dacc[t][0]+b.x)*tanhx(cc[t][0]);
        float h1 = sigf(dacc[t][1]+b.y)*tanhx(cc[t][1]);
        float h2 = sigf(dacc[t][2]+b.x)*tanhx(cc[t][2]);
        float h3 = sigf(dacc[t][3]+b.y)*tanhx(cc[t][3]);
        *(float2*)(g_c + n0*HH + c) = make_float2(cc[t][0], cc[t][1]);
        *(float2*)(g_c + n1*HH + c) = make_float2(cc[t][2], cc[t][3]);
        *(float2*)(g_h + n0*HH + c) = make_float2(h0, h1);
        *(float2*)(g_h + n1*HH + c) = make_float2(h2, h3);
    }
#undef RESTAGE
}

// ---------------------------------------------------------------------------
// Small levels (nl < 128): one parent/block, 512 threads, 9 k-split matvecs.
// dynamic smem: hs 4*128 + part 9*4*128 floats = 75776 B (incl. both).
// ---------------------------------------------------------------------------
__global__ void __launch_bounds__(512) small_level_kernel(
    int sl, const float* __restrict__ x,
    const float* __restrict__ W_i, const float* __restrict__ b_i, const float* __restrict__ U_i,
    const float* __restrict__ W_f, const float* __restrict__ b_f, const float* __restrict__ U_f,
    const float* __restrict__ W_o, const float* __restrict__ b_o, const float* __restrict__ U_o,
    const float* __restrict__ W_u, const float* __restrict__ b_u, const float* __restrict__ U_u)
{
    extern __shared__ float smf[];
    float* hs   = smf;              // [h~ | h0 | h1 | x] x 128
    float* part = smf + 512;        // [9][4][128]

    const int t = threadIdx.x;
    const long node = sl + blockIdx.x;
    const long ch0  = 2*node + 1;

    if (t < 128) {
        float h0 = g_h[ch0*HH + t];
        float h1 = g_h[(ch0+1)*HH + t];
        hs[128+t] = h0; hs[256+t] = h1; hs[t] = h0 + h1;
        hs[384+t] = x[node*HH + t];
    }
    __syncthreads();

    const int col = t & 127;
    const int q   = t >> 7;
    const int kb  = q * 32;

#define JOB(J, S, M) { float av = 0.f; const float* s = hs + (S)*128;          \
        _Pragma("unroll 8")                                                    \
        for (int k = 0; k < 32; ++k) av += s[kb+k] * (M)[(kb+k)*HH + col];     \
        part[((J)*4 + q)*128 + col] = av; }
    JOB(0, 0, U_i) JOB(1, 0, U_o) JOB(2, 0, U_u)
    JOB(3, 1, U_f) JOB(4, 2, U_f)
    JOB(5, 3, W_i) JOB(6, 3, W_f) JOB(7, 3, W_o) JOB(8, 3, W_u)
#undef JOB
    __syncthreads();

    if (t < 128) {
#define SUMP(J) (part[((J)*4+0)*128+t] + part[((J)*4+1)*128+t] + \
                 part[((J)*4+2)*128+t] + part[((J)*4+3)*128+t])
        float yi  = SUMP(0), yo = SUMP(1), yu = SUMP(2);
        float yf0 = SUMP(3), yf1 = SUMP(4);
        float xi  = SUMP(5) + b_i[t];
        float xfv = SUMP(6) + b_f[t];
        float xo  = SUMP(7) + b_o[t];
        float xu  = SUMP(8) + b_u[t];
#undef SUMP
        float c = sigf(xi+yi)*tanhx(xu+yu)
                + sigf(xfv+yf0)*g_c[ch0*HH+t] + sigf(xfv+yf1)*g_c[(ch0+1)*HH+t];
        g_c[node*HH+t] = c;
        g_h[node*HH+t] = sigf(xo+yo)*tanhx(c);
    }
}

__global__ void out_kernel(float* __restrict__ out)
{
    int t = threadIdx.x;
    out[t] = (t < 128) ? g_h[t] : g_c[t - 128];
}

// ---------------------------------------------------------------------------
extern "C" void kernel_launch(void* const* d_in, const int* in_sizes, int n_in,
                              void* d_out, int out_size)
{
    const float* x   = (const float*)d_in[0];
    const float* W_i = (const float*)d_in[1];
    const float* b_i = (const float*)d_in[2];
    const float* U_i = (const float*)d_in[3];
    const float* W_f = (const float*)d_in[4];
    const float* b_f = (const float*)d_in[5];
    const float* U_f = (const float*)d_in[6];
    const float* W_o = (const float*)d_in[7];
    const float* b_o = (const float*)d_in[8];
    const float* U_o = (const float*)d_in[9];
    const float* W_u = (const float*)d_in[10];
    const float* b_u = (const float*)d_in[11];
    const float* U_u = (const float*)d_in[12];

    const int SMEM_T = 6 * SLOT * 2;            // 208896
    const int SMEM_L = 2 * SLOT * 2;            // 69632
    const int SMEM_S = (512 + 9*4*128) * 4;     // 20480... (hs+part)
    cudaFuncSetAttribute(tlevel_kernel, cudaFuncAttributeMaxDynamicSharedMemorySize, SMEM_T);
    cudaFuncSetAttribute(leaf_kernel,   cudaFuncAttributeMaxDynamicSharedMemorySize, SMEM_L);
    cudaFuncSetAttribute(small_level_kernel, cudaFuncAttributeMaxDynamicSharedMemorySize, SMEM_S);

    conv_w_kernel<<<8, 256>>>(W_i, W_f, W_o, W_u, U_i, U_f, U_o, U_u);

    leaf_kernel<<<(1 << DEPTH) / 128, 512, SMEM_L>>>(x, b_i, b_o, b_u);

    for (int l = DEPTH - 1; l >= 0; --l) {
        int nl = 1 << l;
        int sl = nl - 1;
        if (nl >= 128)
            tlevel_kernel<<<nl / 128, 512, SMEM_T>>>(sl, x, b_i, b_f, b_o, b_u);
        else
            small_level_kernel<<<nl, 512, SMEM_S>>>(sl, x,
                W_i, b_i, U_i, W_f, b_f, U_f, W_o, b_o, U_o, W_u, b_u, U_u);
    }

    out_kernel<<<1, 256>>>((float*)d_out);
}

// round 7
// speedup vs baseline: 2.3990x; 1.5857x over previous
#include <cuda_runtime.h>
#include <cuda_bf16.h>
#include <cstdint>

// ---------------------------------------------------------------------------
// ChildSumTreeLSTM depth 17, D=H=128. R7: bf16 HMMA 3-pass split; h~ algebra
// (u/i/o on child-sum, f via G_sum - G1) cuts GEMM units 12->9; M=64 variant
// for underfilled levels.
// ---------------------------------------------------------------------------

#define DEPTH   17
#define HH      128
#define NNODES  ((1 << (DEPTH + 1)) - 1)
#define PITCH   136
#define BSLOT   (128 * PITCH)                    // elems per B half-buffer

__device__ float g_h[33554304L];
__device__ float g_c[33554304L];
// weight images: [mat][hi 2048 uint4 | lo 2048 uint4], dense [k][n] bf16
// mats: 0..3 = W_i,W_f,W_o,W_u ; 4..7 = U_i,U_f,U_o,U_u
__device__ uint4 g_Wb[8][4096];

__device__ __forceinline__ float sigf(float v)  { return 1.0f / (1.0f + __expf(-v)); }
__device__ __forceinline__ float tanhx(float v) {
    float r; asm("tanh.approx.f32 %0, %1;" : "=f"(r) : "f"(v)); return r;
}
__device__ __forceinline__ uint32_t smem_u32(const void* p) {
    uint32_t a; asm("{ .reg .u64 t; cvta.to.shared.u64 t, %1; cvt.u32.u64 %0, t; }"
                    : "=r"(a) : "l"(p)); return a;
}
__device__ __forceinline__ void ldsm4(uint32_t& r0, uint32_t& r1, uint32_t& r2,
                                      uint32_t& r3, uint32_t a) {
    asm volatile("ldmatrix.sync.aligned.m8n8.x4.shared.b16 {%0,%1,%2,%3}, [%4];"
                 : "=r"(r0), "=r"(r1), "=r"(r2), "=r"(r3) : "r"(a));
}
__device__ __forceinline__ void ldsm4t(uint32_t& r0, uint32_t& r1, uint32_t& r2,
                                       uint32_t& r3, uint32_t a) {
    asm volatile("ldmatrix.sync.aligned.m8n8.x4.trans.shared.b16 {%0,%1,%2,%3}, [%4];"
                 : "=r"(r0), "=r"(r1), "=r"(r2), "=r"(r3) : "r"(a));
}
__device__ __forceinline__ void mma16816(float* c, uint32_t a0, uint32_t a1,
                                         uint32_t a2, uint32_t a3,
                                         uint32_t b0, uint32_t b1) {
    asm volatile("mma.sync.aligned.m16n8k16.row.col.f32.bf16.bf16.f32 "
                 "{%0,%1,%2,%3}, {%4,%5,%6,%7}, {%8,%9}, {%0,%1,%2,%3};"
                 : "+f"(c[0]), "+f"(c[1]), "+f"(c[2]), "+f"(c[3])
                 : "r"(a0), "r"(a1), "r"(a2), "r"(a3), "r"(b0), "r"(b1));
}
__device__ __forceinline__ void split2(float a, float b, uint32_t& hi, uint32_t& lo) {
    __nv_bfloat162 h = __floats2bfloat162_rn(a, b);
    float ra = a - __bfloat162float(__low2bfloat16(h));
    float rb = b - __bfloat162float(__high2bfloat16(h));
    __nv_bfloat162 l = __floats2bfloat162_rn(ra, rb);
    hi = *(uint32_t*)&h; lo = *(uint32_t*)&l;
}

#define INNER_J(DACC, BHP, BLP)                                                \
    _Pragma("unroll")                                                          \
    for (int j = 0; j < 4; ++j) {                                              \
        uint32_t bh0,bh1,bh2,bh3, bl0,bl1,bl2,bl3;                             \
        ldsm4t(bh0,bh1,bh2,bh3, (BHP) + j*32);                                 \
        ldsm4t(bl0,bl1,bl2,bl3, (BLP) + j*32);                                 \
        mma16816(DACC[2*j],   ah0,ah1,ah2,ah3, bh0,bh1);                       \
        mma16816(DACC[2*j+1], ah0,ah1,ah2,ah3, bh2,bh3);                       \
        mma16816(DACC[2*j],   ah0,ah1,ah2,ah3, bl0,bl1);                       \
        mma16816(DACC[2*j+1], ah0,ah1,ah2,ah3, bl2,bl3);                       \
        mma16816(DACC[2*j],   al0,al1,al2,al3, bh0,bh1);                       \
        mma16816(DACC[2*j+1], al0,al1,al2,al3, bh2,bh3);                       \
    }

__device__ __forceinline__ void gemm_S(float (*dacc)[4], uint32_t aH, uint32_t aL,
                                       uint32_t bH, uint32_t bL)
{
#pragma unroll
    for (int kc = 0; kc < 8; ++kc) {
        uint32_t ah0,ah1,ah2,ah3, al0,al1,al2,al3;
        ldsm4(ah0,ah1,ah2,ah3, aH + kc*32);
        ldsm4(al0,al1,al2,al3, aL + kc*32);
        uint32_t bhp = bH + kc*(16*PITCH*2), blp = bL + kc*(16*PITCH*2);
        INNER_J(dacc, bhp, blp)
    }
}

__device__ __forceinline__ void gemm_X(float (*dacc)[4],
                                       const float* __restrict__ xA,
                                       const float* __restrict__ xB,
                                       int qc2, uint32_t bH, uint32_t bL)
{
#pragma unroll
    for (int kc = 0; kc < 8; ++kc) {
        int k0 = kc*16 + qc2;
        float2 v0 = *(const float2*)(xA + k0);
        float2 v1 = *(const float2*)(xB + k0);
        float2 v2 = *(const float2*)(xA + k0 + 8);
        float2 v3 = *(const float2*)(xB + k0 + 8);
        uint32_t ah0,al0,ah1,al1,ah2,al2,ah3,al3;
        split2(v0.x,v0.y,ah0,al0); split2(v1.x,v1.y,ah1,al1);
        split2(v2.x,v2.y,ah2,al2); split2(v3.x,v3.y,ah3,al3);
        uint32_t bhp = bH + kc*(16*PITCH*2), blp = bL + kc*(16*PITCH*2);
        INNER_J(dacc, bhp, blp)
    }
}

__device__ __forceinline__ void stage_B(__nv_bfloat16* Bh, __nv_bfloat16* Bl,
                                        int mat, int tid, int nthr)
{
    const uint4* src = g_Wb[mat];
    for (int i = tid; i < 2048; i += nthr) {
        int row = i >> 4, ch = i & 15;
        *(uint4*)(Bh + row * PITCH + ch * 8) = src[i];
        *(uint4*)(Bl + row * PITCH + ch * 8) = src[i + 2048];
    }
}

__global__ void conv_w_kernel(
    const float* __restrict__ W_i, const float* __restrict__ W_f,
    const float* __restrict__ W_o, const float* __restrict__ W_u,
    const float* __restrict__ U_i, const float* __restrict__ U_f,
    const float* __restrict__ U_o, const float* __restrict__ U_u)
{
    const float* mats[8] = { W_i, W_f, W_o, W_u, U_i, U_f, U_o, U_u };
    const float* M = mats[blockIdx.x];
    __nv_bfloat16* hi = (__nv_bfloat16*)&g_Wb[blockIdx.x][0];
    __nv_bfloat16* lo = hi + 16384;
    for (int idx = threadIdx.x; idx < 16384; idx += blockDim.x) {
        float v = M[idx];
        __nv_bfloat16 h = __float2bfloat16(v);
        hi[idx] = h;
        lo[idx] = __float2bfloat16(v - __bfloat162float(h));
    }
}

#define ZERO(D) { _Pragma("unroll") for (int t = 0; t < 8; ++t) \
        { D[t][0]=0.f; D[t][1]=0.f; D[t][2]=0.f; D[t][3]=0.f; } }

// ---------------------------------------------------------------------------
// Leaf: 128 leaves/block, 3 gemm_X (u,i,o). smem 69632 B -> up to 3 CTA/SM.
// ---------------------------------------------------------------------------
__global__ void __launch_bounds__(512) leaf_kernel(
    const float* __restrict__ x,
    const float* __restrict__ b_i, const float* __restrict__ b_o,
    const float* __restrict__ b_u)
{
    extern __shared__ __align__(16) __nv_bfloat16 sm[];
    __nv_bfloat16* Bh = sm;
    __nv_bfloat16* Bl = sm + BSLOT;

    const int tid = threadIdx.x;
    const int w = tid >> 5, l = tid & 31;
    const int mg = w >> 1, nh = w & 1;
    const int lr = l & 15, lc = l >> 4;
    const int qr = l >> 2, qc2 = (l & 3) * 2;

    const long n0 = (long)((1 << DEPTH) - 1) + (long)blockIdx.x * 128 + mg*16 + qr;
    const long n1 = n0 + 8;
    const float* xA = x + n0*HH;
    const float* xB = x + n1*HH;
    const int cbase = nh*64 + qc2;

    const uint32_t b_off = (uint32_t)(lr*PITCH + nh*64 + lc*8)*2;
    const uint32_t bH = smem_u32(Bh)+b_off, bL = smem_u32(Bl)+b_off;

    float dacc[8][4], cc[8][4];

    stage_B(Bh, Bl, 3, tid, 512);           // W_u
    __syncthreads();
    ZERO(dacc); gemm_X(dacc, xA, xB, qc2, bH, bL);
#pragma unroll
    for (int t = 0; t < 8; ++t) {
        float2 b = *(const float2*)(b_u + cbase + t*8);
        cc[t][0]=tanhx(dacc[t][0]+b.x); cc[t][1]=tanhx(dacc[t][1]+b.y);
        cc[t][2]=tanhx(dacc[t][2]+b.x); cc[t][3]=tanhx(dacc[t][3]+b.y);
    }
    __syncthreads(); stage_B(Bh, Bl, 0, tid, 512); __syncthreads();   // W_i
    ZERO(dacc); gemm_X(dacc, xA, xB, qc2, bH, bL);
#pragma unroll
    for (int t = 0; t < 8; ++t) {
        float2 b = *(const float2*)(b_i + cbase + t*8);
        cc[t][0]*=sigf(dacc[t][0]+b.x); cc[t][1]*=sigf(dacc[t][1]+b.y);
        cc[t][2]*=sigf(dacc[t][2]+b.x); cc[t][3]*=sigf(dacc[t][3]+b.y);
    }
    __syncthreads(); stage_B(Bh, Bl, 2, tid, 512); __syncthreads();   // W_o
    ZERO(dacc); gemm_X(dacc, xA, xB, qc2, bH, bL);
#pragma unroll
    for (int t = 0; t < 8; ++t) {
        int c = cbase + t*8;
        float2 b = *(const float2*)(b_o + c);
        float h0 = sigf(dacc[t][0]+b.x)*tanhx(cc[t][0]);
        float h1 = sigf(dacc[t][1]+b.y)*tanhx(cc[t][1]);
        float h2 = sigf(dacc[t][2]+b.x)*tanhx(cc[t][2]);
        float h3 = sigf(dacc[t][3]+b.y)*tanhx(cc[t][3]);
        *(float2*)(g_c + n0*HH + c) = make_float2(cc[t][0], cc[t][1]);
        *(float2*)(g_c + n1*HH + c) = make_float2(cc[t][2], cc[t][3]);
        *(float2*)(g_h + n0*HH + c) = make_float2(h0, h1);
        *(float2*)(g_h + n1*HH + c) = make_float2(h2, h3);
    }
}

// ---------------------------------------------------------------------------
// Tensor level kernel, MROWS parents/block, 4*MROWS threads.
// A slots: S_sum = split(h0+h1), S1 = split(h1). 9 GEMM units:
//   u: X(W_u) + S(sum,U_u) ; i: X(W_i) + S(sum,U_i)
//   f: X(W_f)=xf; G1=S(s1,U_f) -> f1; dacc=-G1; +S(sum,U_f)=G0 -> f0
//   o: X(W_o) + S(sum,U_o)
// smem: 4 S slots (MROWS*PITCH) + 2 B slots (128*PITCH), bf16.
// ---------------------------------------------------------------------------
template<int MROWS>
__global__ void __launch_bounds__(MROWS * 4) tlevel_kernel(
    int sl, const float* __restrict__ x,
    const float* __restrict__ b_i, const float* __restrict__ b_f,
    const float* __restrict__ b_o, const float* __restrict__ b_u)
{
    constexpr int SS = MROWS * PITCH;
    constexpr int NTHR = MROWS * 4;
    extern __shared__ __align__(16) __nv_bfloat16 sm[];
    __nv_bfloat16* SUh = sm;                 // S_sum hi
    __nv_bfloat16* SUl = sm + SS;
    __nv_bfloat16* S1h = sm + 2*SS;          // S1 hi
    __nv_bfloat16* S1l = sm + 3*SS;
    __nv_bfloat16* Bh  = sm + 4*SS;
    __nv_bfloat16* Bl  = sm + 4*SS + BSLOT;

    const int tid = threadIdx.x;
    const int w = tid >> 5, l = tid & 31;
    const int mg = w >> 1, nh = w & 1;
    const int lr = l & 15, lc = l >> 4;
    const int qr = l >> 2, qc2 = (l & 3) * 2;

    const long np = (long)sl + (long)blockIdx.x * MROWS;
    const long cb = 2*np + 1;

    // convert: rows [0,MROWS): S_sum(parent row)=h0+h1; rows [MROWS,2M): S1=h1
    {
        int row_idx = tid >> 1;
        int half = (tid & 1) * 64;
        bool is_sum = (row_idx < MROWS);
        int p = is_sum ? row_idx : row_idx - MROWS;
        const float* s0 = g_h + (cb + 2*p) * HH + half;
        __nv_bfloat16* dh = is_sum ? SUh : S1h;
        __nv_bfloat16* dl = is_sum ? SUl : S1l;
#pragma unroll
        for (int i = 0; i < 16; ++i) {
            float4 v;
            if (is_sum) {
                float4 a = *(const float4*)(s0 + i*4);
                float4 b = *(const float4*)(s0 + HH + i*4);
                v = make_float4(a.x+b.x, a.y+b.y, a.z+b.z, a.w+b.w);
            } else {
                v = *(const float4*)(s0 + HH + i*4);
            }
            uint32_t h0,l0,h1,l1;
            split2(v.x,v.y,h0,l0); split2(v.z,v.w,h1,l1);
            *(uint2*)(dh + p*PITCH + half + i*4) = make_uint2(h0,h1);
            *(uint2*)(dl + p*PITCH + half + i*4) = make_uint2(l0,l1);
        }
    }
    stage_B(Bh, Bl, 3, tid, NTHR);           // W_u
    __syncthreads();

    const uint32_t a_off = (uint32_t)((16*mg + lr)*PITCH + lc*8)*2;
    const uint32_t b_off = (uint32_t)(lr*PITCH + nh*64 + lc*8)*2;
    const uint32_t sUH = smem_u32(SUh)+a_off, sUL = smem_u32(SUl)+a_off;
    const uint32_t s1H = smem_u32(S1h)+a_off, s1L = smem_u32(S1l)+a_off;
    const uint32_t bH = smem_u32(Bh)+b_off, bL = smem_u32(Bl)+b_off;

    const long n0 = np + mg*16 + qr, n1 = n0 + 8;
    const float* xA = x + n0*HH;
    const float* xB = x + n1*HH;
    const int cbase = nh*64 + qc2;

    float dacc[8][4], cc[8][4], xf[8][4];

#define RESTAGE(M) do { __syncthreads(); stage_B(Bh, Bl, M, tid, NTHR); \
        __syncthreads(); } while (0)

    // ---- u ----
    ZERO(dacc); gemm_X(dacc, xA, xB, qc2, bH, bL);
    RESTAGE(7);
    gemm_S(dacc, sUH, sUL, bH, bL);
#pragma unroll
    for (int t = 0; t < 8; ++t) {
        float2 b = *(const float2*)(b_u + cbase + t*8);
        cc[t][0]=tanhx(dacc[t][0]+b.x); cc[t][1]=tanhx(dacc[t][1]+b.y);
        cc[t][2]=tanhx(dacc[t][2]+b.x); cc[t][3]=tanhx(dacc[t][3]+b.y);
    }
    // ---- i ----
    RESTAGE(0);
    ZERO(dacc); gemm_X(dacc, xA, xB, qc2, bH, bL);
    RESTAGE(4);
    gemm_S(dacc, sUH, sUL, bH, bL);
#pragma unroll
    for (int t = 0; t < 8; ++t) {
        float2 b = *(const float2*)(b_i + cbase + t*8);
        cc[t][0]*=sigf(dacc[t][0]+b.x); cc[t][1]*=sigf(dacc[t][1]+b.y);
        cc[t][2]*=sigf(dacc[t][2]+b.x); cc[t][3]*=sigf(dacc[t][3]+b.y);
    }
    // ---- f ----
    RESTAGE(1);
    ZERO(dacc); gemm_X(dacc, xA, xB, qc2, bH, bL);
#pragma unroll
    for (int t = 0; t < 8; ++t) {
        float2 b = *(const float2*)(b_f + cbase + t*8);
        xf[t][0]=dacc[t][0]+b.x; xf[t][1]=dacc[t][1]+b.y;
        xf[t][2]=dacc[t][2]+b.x; xf[t][3]=dacc[t][3]+b.y;
    }
    RESTAGE(5);
    ZERO(dacc); gemm_S(dacc, s1H, s1L, bH, bL);       // G1 = h1 @ U_f
#pragma unroll
    for (int t = 0; t < 8; ++t) {                     // f1 uses child1 cell
        int c = cbase + t*8;
        float2 ca = *(const float2*)(g_c + (2*n0+2)*HH + c);
        float2 cbv = *(const float2*)(g_c + (2*n1+2)*HH + c);
        cc[t][0]+=sigf(dacc[t][0]+xf[t][0])*ca.x;
        cc[t][1]+=sigf(dacc[t][1]+xf[t][1])*ca.y;
        cc[t][2]+=sigf(dacc[t][2]+xf[t][2])*cbv.x;
        cc[t][3]+=sigf(dacc[t][3]+xf[t][3])*cbv.y;
        dacc[t][0]=-dacc[t][0]; dacc[t][1]=-dacc[t][1];
        dacc[t][2]=-dacc[t][2]; dacc[t][3]=-dacc[t][3];
    }
    gemm_S(dacc, sUH, sUL, bH, bL);                   // G_sum - G1 = h0 @ U_f
#pragma unroll
    for (int t = 0; t < 8; ++t) {                     // f0 uses child0 cell
        int c = cbase + t*8;
        float2 ca = *(const float2*)(g_c + (2*n0+1)*HH + c);
        float2 cbv = *(const float2*)(g_c + (2*n1+1)*HH + c);
        cc[t][0]+=sigf(dacc[t][0]+xf[t][0])*ca.x;
        cc[t][1]+=sigf(dacc[t][1]+xf[t][1])*ca.y;
        cc[t][2]+=sigf(dacc[t][2]+xf[t][2])*cbv.x;
        cc[t][3]+=sigf(dacc[t][3]+xf[t][3])*cbv.y;
    }
    // ---- o + store ----
    RESTAGE(2);
    ZERO(dacc); gemm_X(dacc, xA, xB, qc2, bH, bL);
    RESTAGE(6);
    gemm_S(dacc, sUH, sUL, bH, bL);
#pragma unroll
    for (int t = 0; t < 8; ++t) {
        int c = cbase + t*8;
        float2 b = *(const float2*)(b_o + c);
        float h0 = sigf(dacc[t][0]+b.x)*tanhx(cc[t][0]);
        float h1 = sigf(dacc[t][1]+b.y)*tanhx(cc[t][1]);
        float h2 = sigf(dacc[t][2]+b.x)*tanhx(cc[t][2]);
        float h3 = sigf(dacc[t][3]+b.y)*tanhx(cc[t][3]);
        *(float2*)(g_c + n0*HH + c) = make_float2(cc[t][0], cc[t][1]);
        *(float2*)(g_c + n1*HH + c) = make_float2(cc[t][2], cc[t][3]);
        *(float2*)(g_h + n0*HH + c) = make_float2(h0, h1);
        *(float2*)(g_h + n1*HH + c) = make_float2(h2, h3);
    }
#undef RESTAGE
}

// ---------------------------------------------------------------------------
// Small levels (nl < 128): one parent/block, 512 threads, 9 k-split matvecs.
// ---------------------------------------------------------------------------
__global__ void __launch_bounds__(512) small_level_kernel(
    int sl, const float* __restrict__ x,
    const float* __restrict__ W_i, const float* __restrict__ b_i, const float* __restrict__ U_i,
    const float* __restrict__ W_f, const float* __restrict__ b_f, const float* __restrict__ U_f,
    const float* __restrict__ W_o, const float* __restrict__ b_o, const float* __restrict__ U_o,
    const float* __restrict__ W_u, const float* __restrict__ b_u, const float* __restrict__ U_u)
{
    extern __shared__ float smf[];
    float* hs   = smf;              // [h~ | h0 | h1 | x] x 128
    float* part = smf + 512;        // [9][4][128]

    const int t = threadIdx.x;
    const long node = sl + blockIdx.x;
    const long ch0  = 2*node + 1;

    if (t < 128) {
        float h0 = g_h[ch0*HH + t];
        float h1 = g_h[(ch0+1)*HH + t];
        hs[128+t] = h0; hs[256+t] = h1; hs[t] = h0 + h1;
        hs[384+t] = x[node*HH + t];
    }
    __syncthreads();

    const int col = t & 127;
    const int q   = t >> 7;
    const int kb  = q * 32;

#define JOB(J, S, M) { float av = 0.f; const float* s = hs + (S)*128;          \
        _Pragma("unroll 8")                                                    \
        for (int k = 0; k < 32; ++k) av += s[kb+k] * (M)[(kb+k)*HH + col];     \
        part[((J)*4 + q)*128 + col] = av; }
    JOB(0, 0, U_i) JOB(1, 0, U_o) JOB(2, 0, U_u)
    JOB(3, 1, U_f) JOB(4, 2, U_f)
    JOB(5, 3, W_i) JOB(6, 3, W_f) JOB(7, 3, W_o) JOB(8, 3, W_u)
#undef JOB
    __syncthreads();

    if (t < 128) {
#define SUMP(J) (part[((J)*4+0)*128+t] + part[((J)*4+1)*128+t] + \
                 part[((J)*4+2)*128+t] + part[((J)*4+3)*128+t])
        float yi  = SUMP(0), yo = SUMP(1), yu = SUMP(2);
        float yf0 = SUMP(3), yf1 = SUMP(4);
        float xi  = SUMP(5) + b_i[t];
        float xfv = SUMP(6) + b_f[t];
        float xo  = SUMP(7) + b_o[t];
        float xu  = SUMP(8) + b_u[t];
#undef SUMP
        float c = sigf(xi+yi)*tanhx(xu+yu)
                + sigf(xfv+yf0)*g_c[ch0*HH+t] + sigf(xfv+yf1)*g_c[(ch0+1)*HH+t];
        g_c[node*HH+t] = c;
        g_h[node*HH+t] = sigf(xo+yo)*tanhx(c);
    }
}

__global__ void out_kernel(float* __restrict__ out)
{
    int t = threadIdx.x;
    out[t] = (t < 128) ? g_h[t] : g_c[t - 128];
}

// ---------------------------------------------------------------------------
extern "C" void kernel_launch(void* const* d_in, const int* in_sizes, int n_in,
                              void* d_out, int out_size)
{
    const float* x   = (const float*)d_in[0];
    const float* W_i = (const float*)d_in[1];
    const float* b_i = (const float*)d_in[2];
    const float* U_i = (const float*)d_in[3];
    const float* W_f = (const float*)d_in[4];
    const float* b_f = (const float*)d_in[5];
    const float* U_f = (const float*)d_in[6];
    const float* W_o = (const float*)d_in[7];
    const float* b_o = (const float*)d_in[8];
    const float* U_o = (const float*)d_in[9];
    const float* W_u = (const float*)d_in[10];
    const float* b_u = (const float*)d_in[11];
    const float* U_u = (const float*)d_in[12];

    const int SMEM_T128 = (4*128*PITCH + 2*BSLOT) * 2;   // 208896
    const int SMEM_T64  = (4*64*PITCH  + 2*BSLOT) * 2;   // 139264
    const int SMEM_L    = 2 * BSLOT * 2;                 // 69632
    const int SMEM_S    = (512 + 9*4*128) * 4;
    cudaFuncSetAttribute(tlevel_kernel<128>, cudaFuncAttributeMaxDynamicSharedMemorySize, SMEM_T128);
    cudaFuncSetAttribute(tlevel_kernel<64>,  cudaFuncAttributeMaxDynamicSharedMemorySize, SMEM_T64);
    cudaFuncSetAttribute(leaf_kernel,        cudaFuncAttributeMaxDynamicSharedMemorySize, SMEM_L);
    cudaFuncSetAttribute(small_level_kernel, cudaFuncAttributeMaxDynamicSharedMemorySize, SMEM_S);

    conv_w_kernel<<<8, 256>>>(W_i, W_f, W_o, W_u, U_i, U_f, U_o, U_u);

    leaf_kernel<<<(1 << DEPTH) / 128, 512, SMEM_L>>>(x, b_i, b_o, b_u);

    for (int l = DEPTH - 1; l >= 0; --l) {
        int nl = 1 << l;
        int sl = nl - 1;
        if (nl >= 16384)
            tlevel_kernel<128><<<nl / 128, 512, SMEM_T128>>>(sl, x, b_i, b_f, b_o, b_u);
        else if (nl >= 128)
            tlevel_kernel<64><<<nl / 64, 256, SMEM_T64>>>(sl, x, b_i, b_f, b_o, b_u);
        else
            small_level_kernel<<<nl, 512, SMEM_S>>>(sl, x,
                W_i, b_i, U_i, W_f, b_f, U_f, W_o, b_o, U_o, W_u, b_u, U_u);
    }

    out_kernel<<<1, 256>>>((float*)d_out);
}

// round 8
// speedup vs baseline: 2.9561x; 1.2322x over previous
#include <cuda_runtime.h>
#include <cuda_bf16.h>
#include <cstdint>

// ---------------------------------------------------------------------------
// ChildSumTreeLSTM depth 17, D=H=128. R8: all-smem HMMA GEMMs (x staged once,
// bf16 hi/lo 3-pass split), register-prefetched B staging (global latency
// hidden), M=64 x 512-thread tlevel, h~ algebra for f gates.
// ---------------------------------------------------------------------------

#define DEPTH   17
#define HH      128
#define NNODES  ((1 << (DEPTH + 1)) - 1)
#define PITCH   136

__device__ float g_h[33554304L];
__device__ float g_c[33554304L];
// weight images: [mat][hi 2048 uint4 | lo 2048 uint4], dense [k][n] bf16
// mats: 0..3 = W_i,W_f,W_o,W_u ; 4..7 = U_i,U_f,U_o,U_u
__device__ uint4 g_Wb[8][4096];

__device__ __forceinline__ float sigf(float v)  { return 1.0f / (1.0f + __expf(-v)); }
__device__ __forceinline__ float tanhx(float v) {
    float r; asm("tanh.approx.f32 %0, %1;" : "=f"(r) : "f"(v)); return r;
}
__device__ __forceinline__ uint32_t smem_u32(const void* p) {
    uint32_t a; asm("{ .reg .u64 t; cvta.to.shared.u64 t, %1; cvt.u32.u64 %0, t; }"
                    : "=r"(a) : "l"(p)); return a;
}
__device__ __forceinline__ void ldsm4(uint32_t& r0, uint32_t& r1, uint32_t& r2,
                                      uint32_t& r3, uint32_t a) {
    asm volatile("ldmatrix.sync.aligned.m8n8.x4.shared.b16 {%0,%1,%2,%3}, [%4];"
                 : "=r"(r0), "=r"(r1), "=r"(r2), "=r"(r3) : "r"(a));
}
__device__ __forceinline__ void ldsm4t(uint32_t& r0, uint32_t& r1, uint32_t& r2,
                                       uint32_t& r3, uint32_t a) {
    asm volatile("ldmatrix.sync.aligned.m8n8.x4.trans.shared.b16 {%0,%1,%2,%3}, [%4];"
                 : "=r"(r0), "=r"(r1), "=r"(r2), "=r"(r3) : "r"(a));
}
__device__ __forceinline__ void mma16816(float* c, uint32_t a0, uint32_t a1,
                                         uint32_t a2, uint32_t a3,
                                         uint32_t b0, uint32_t b1) {
    asm volatile("mma.sync.aligned.m16n8k16.row.col.f32.bf16.bf16.f32 "
                 "{%0,%1,%2,%3}, {%4,%5,%6,%7}, {%8,%9}, {%0,%1,%2,%3};"
                 : "+f"(c[0]), "+f"(c[1]), "+f"(c[2]), "+f"(c[3])
                 : "r"(a0), "r"(a1), "r"(a2), "r"(a3), "r"(b0), "r"(b1));
}
__device__ __forceinline__ void split2(float a, float b, uint32_t& hi, uint32_t& lo) {
    __nv_bfloat162 h = __floats2bfloat162_rn(a, b);
    float ra = a - __bfloat162float(__low2bfloat16(h));
    float rb = b - __bfloat162float(__high2bfloat16(h));
    __nv_bfloat162 l = __floats2bfloat162_rn(ra, rb);
    hi = *(uint32_t*)&h; lo = *(uint32_t*)&l;
}

// all-smem 3-pass GEMM; NT = number of 16-col groups this warp covers.
template<int NT>
__device__ __forceinline__ void gemm_S(float (*dacc)[4], uint32_t aH, uint32_t aL,
                                       uint32_t bH, uint32_t bL)
{
#pragma unroll
    for (int kc = 0; kc < 8; ++kc) {
        uint32_t ah0,ah1,ah2,ah3, al0,al1,al2,al3;
        ldsm4(ah0,ah1,ah2,ah3, aH + kc*32);
        ldsm4(al0,al1,al2,al3, aL + kc*32);
        uint32_t bhp = bH + kc*(16*PITCH*2), blp = bL + kc*(16*PITCH*2);
#pragma unroll
        for (int j = 0; j < NT; ++j) {
            uint32_t bh0,bh1,bh2,bh3, bl0,bl1,bl2,bl3;
            ldsm4t(bh0,bh1,bh2,bh3, bhp + j*32);
            ldsm4t(bl0,bl1,bl2,bl3, blp + j*32);
            mma16816(dacc[2*j],   ah0,ah1,ah2,ah3, bh0,bh1);
            mma16816(dacc[2*j+1], ah0,ah1,ah2,ah3, bh2,bh3);
            mma16816(dacc[2*j],   ah0,ah1,ah2,ah3, bl0,bl1);
            mma16816(dacc[2*j+1], ah0,ah1,ah2,ah3, bl2,bl3);
            mma16816(dacc[2*j],   al0,al1,al2,al3, bh0,bh1);
            mma16816(dacc[2*j+1], al0,al1,al2,al3, bh2,bh3);
        }
    }
}

// register-prefetch B staging (512-thread kernels): 4 hi + 4 lo uint4 / thread
__device__ __forceinline__ void ldB(uint4* r, int mat, int tid) {
    const uint4* src = g_Wb[mat];
#pragma unroll
    for (int q = 0; q < 4; ++q) {
        r[q]     = src[tid + q*512];
        r[q + 4] = src[tid + q*512 + 2048];
    }
}
__device__ __forceinline__ void stB(__nv_bfloat16* Bh, __nv_bfloat16* Bl,
                                    const uint4* r, int tid) {
#pragma unroll
    for (int q = 0; q < 4; ++q) {
        int i = tid + q*512, row = i >> 4, ch = i & 15;
        *(uint4*)(Bh + row*PITCH + ch*8) = r[q];
        *(uint4*)(Bl + row*PITCH + ch*8) = r[q + 4];
    }
}

__global__ void conv_w_kernel(
    const float* __restrict__ W_i, const float* __restrict__ W_f,
    const float* __restrict__ W_o, const float* __restrict__ W_u,
    const float* __restrict__ U_i, const float* __restrict__ U_f,
    const float* __restrict__ U_o, const float* __restrict__ U_u)
{
    const float* mats[8] = { W_i, W_f, W_o, W_u, U_i, U_f, U_o, U_u };
    const float* M = mats[blockIdx.x];
    __nv_bfloat16* hi = (__nv_bfloat16*)&g_Wb[blockIdx.x][0];
    __nv_bfloat16* lo = hi + 16384;
    for (int idx = threadIdx.x; idx < 16384; idx += blockDim.x) {
        float v = M[idx];
        __nv_bfloat16 h = __float2bfloat16(v);
        hi[idx] = h;
        lo[idx] = __float2bfloat16(v - __bfloat162float(h));
    }
}

// convert one fp32 row-half into bf16 hi/lo smem (helper body)
__device__ __forceinline__ void conv_row(__nv_bfloat16* dh, __nv_bfloat16* dl,
                                         int row, int half,
                                         const float* __restrict__ s0,
                                         const float* __restrict__ s1)
{
#pragma unroll
    for (int i = 0; i < 16; ++i) {
        float4 v = *(const float4*)(s0 + i*4);
        if (s1) {
            float4 w = *(const float4*)(s1 + i*4);
            v.x += w.x; v.y += w.y; v.z += w.z; v.w += w.w;
        }
        uint32_t h0,l0,h1,l1;
        split2(v.x,v.y,h0,l0); split2(v.z,v.w,h1,l1);
        *(uint2*)(dh + row*PITCH + half + i*4) = make_uint2(h0,h1);
        *(uint2*)(dl + row*PITCH + half + i*4) = make_uint2(l0,l1);
    }
}

// ---------------------------------------------------------------------------
// Leaf: 128 leaves/block, 512 threads. x staged to smem once; gates u,i,o.
// smem: Xh,Xl,Bh,Bl each 128*PITCH -> 139264 B.
// ---------------------------------------------------------------------------
__global__ void __launch_bounds__(512) leaf_kernel(
    const float* __restrict__ x,
    const float* __restrict__ b_i, const float* __restrict__ b_o,
    const float* __restrict__ b_u)
{
    extern __shared__ __align__(16) __nv_bfloat16 sm[];
    __nv_bfloat16* Xh = sm;
    __nv_bfloat16* Xl = sm + 128*PITCH;
    __nv_bfloat16* Bh = sm + 2*128*PITCH;
    __nv_bfloat16* Bl = sm + 3*128*PITCH;

    const int tid = threadIdx.x;
    const int w = tid >> 5, l = tid & 31;
    const int mg = w >> 1, nh = w & 1;
    const int lr = l & 15, lc = l >> 4;
    const int qr = l >> 2, qc2 = (l & 3) * 2;
    const long np = (long)((1 << DEPTH) - 1) + (long)blockIdx.x * 128;

    uint4 breg[8];
    ldB(breg, 3, tid);                      // W_u
    if (tid < 256) {
        int row = tid >> 1, half = (tid & 1) * 64;
        conv_row(Xh, Xl, row, half, x + (np + row)*HH + half, nullptr);
    }
    stB(Bh, Bl, breg, tid);
    __syncthreads();

    const uint32_t a_off = (uint32_t)((16*mg + lr)*PITCH + lc*8)*2;
    const uint32_t b_off = (uint32_t)(lr*PITCH + nh*64 + lc*8)*2;
    const uint32_t xH = smem_u32(Xh)+a_off, xL = smem_u32(Xl)+a_off;
    const uint32_t bH = smem_u32(Bh)+b_off, bL = smem_u32(Bl)+b_off;

    const long n0 = np + 16*mg + qr, n1 = n0 + 8;
    const int cbase = nh*64 + qc2;

    float dacc[8][4], cc[8][4];
#define ZERO8 { _Pragma("unroll") for (int t = 0; t < 8; ++t) \
        { dacc[t][0]=0.f; dacc[t][1]=0.f; dacc[t][2]=0.f; dacc[t][3]=0.f; } }
#define SWAPB() do { __syncthreads(); stB(Bh, Bl, breg, tid); __syncthreads(); } while (0)

    ldB(breg, 0, tid);                      // W_i prefetch
    ZERO8; gemm_S<4>(dacc, xH, xL, bH, bL); // x @ W_u
#pragma unroll
    for (int t = 0; t < 8; ++t) {
        float2 b = *(const float2*)(b_u + cbase + t*8);
        cc[t][0]=tanhx(dacc[t][0]+b.x); cc[t][1]=tanhx(dacc[t][1]+b.y);
        cc[t][2]=tanhx(dacc[t][2]+b.x); cc[t][3]=tanhx(dacc[t][3]+b.y);
    }
    SWAPB();                                // B = W_i
    ldB(breg, 2, tid);                      // W_o prefetch
    ZERO8; gemm_S<4>(dacc, xH, xL, bH, bL);
#pragma unroll
    for (int t = 0; t < 8; ++t) {
        float2 b = *(const float2*)(b_i + cbase + t*8);
        cc[t][0]*=sigf(dacc[t][0]+b.x); cc[t][1]*=sigf(dacc[t][1]+b.y);
        cc[t][2]*=sigf(dacc[t][2]+b.x); cc[t][3]*=sigf(dacc[t][3]+b.y);
    }
    SWAPB();                                // B = W_o
    ZERO8; gemm_S<4>(dacc, xH, xL, bH, bL);
#pragma unroll
    for (int t = 0; t < 8; ++t) {
        int c = cbase + t*8;
        float2 b = *(const float2*)(b_o + c);
        float h0 = sigf(dacc[t][0]+b.x)*tanhx(cc[t][0]);
        float h1 = sigf(dacc[t][1]+b.y)*tanhx(cc[t][1]);
        float h2 = sigf(dacc[t][2]+b.x)*tanhx(cc[t][2]);
        float h3 = sigf(dacc[t][3]+b.y)*tanhx(cc[t][3]);
        *(float2*)(g_c + n0*HH + c) = make_float2(cc[t][0], cc[t][1]);
        *(float2*)(g_c + n1*HH + c) = make_float2(cc[t][2], cc[t][3]);
        *(float2*)(g_h + n0*HH + c) = make_float2(h0, h1);
        *(float2*)(g_h + n1*HH + c) = make_float2(h2, h3);
    }
#undef ZERO8
#undef SWAPB
}

// ---------------------------------------------------------------------------
// Tensor level kernel: 64 parents/block, 512 threads (4 row-grp x 4 col-slice).
// A slots: X (x rows), SUM (h0+h1), S1 (h1), all bf16 hi/lo in smem.
// smem: 6*64*PITCH + 2*128*PITCH = 174080 B.
// ---------------------------------------------------------------------------
__global__ void __launch_bounds__(512) tlevel_kernel(
    int sl, const float* __restrict__ x,
    const float* __restrict__ b_i, const float* __restrict__ b_f,
    const float* __restrict__ b_o, const float* __restrict__ b_u)
{
    constexpr int AS = 64 * PITCH;
    extern __shared__ __align__(16) __nv_bfloat16 sm[];
    __nv_bfloat16* Xh  = sm;
    __nv_bfloat16* Xl  = sm + AS;
    __nv_bfloat16* SUh = sm + 2*AS;
    __nv_bfloat16* SUl = sm + 3*AS;
    __nv_bfloat16* S1h = sm + 4*AS;
    __nv_bfloat16* S1l = sm + 5*AS;
    __nv_bfloat16* Bh  = sm + 6*AS;
    __nv_bfloat16* Bl  = sm + 6*AS + 128*PITCH;

    const int tid = threadIdx.x;
    const int w = tid >> 5, l = tid & 31;
    const int mg = w >> 2, nh = w & 3;
    const int lr = l & 15, lc = l >> 4;
    const int qr = l >> 2, qc2 = (l & 3) * 2;

    const long np = (long)sl + (long)blockIdx.x * 64;
    const long cb = 2*np + 1;

    uint4 breg[8];
    ldB(breg, 3, tid);                      // W_u
    if (tid < 384) {
        int slot = tid >> 7;                // 0=X, 1=SUM, 2=S1
        int row  = (tid & 127) >> 1;
        int half = (tid & 1) * 64;
        if (slot == 0)
            conv_row(Xh, Xl, row, half, x + (np + row)*HH + half, nullptr);
        else if (slot == 1)
            conv_row(SUh, SUl, row, half, g_h + (cb + 2*row)*HH + half,
                                          g_h + (cb + 2*row + 1)*HH + half);
        else
            conv_row(S1h, S1l, row, half, g_h + (cb + 2*row + 1)*HH + half, nullptr);
    }
    stB(Bh, Bl, breg, tid);
    __syncthreads();

    const uint32_t a_off = (uint32_t)((16*mg + lr)*PITCH + lc*8)*2;
    const uint32_t b_off = (uint32_t)(lr*PITCH + nh*32 + lc*8)*2;
    const uint32_t xH  = smem_u32(Xh)+a_off,  xL  = smem_u32(Xl)+a_off;
    const uint32_t suH = smem_u32(SUh)+a_off, suL = smem_u32(SUl)+a_off;
    const uint32_t s1H = smem_u32(S1h)+a_off, s1L = smem_u32(S1l)+a_off;
    const uint32_t bH  = smem_u32(Bh)+b_off,  bL  = smem_u32(Bl)+b_off;

    const long n0 = np + 16*mg + qr, n1 = n0 + 8;
    const int cbase = nh*32 + qc2;

    float dacc[4][4], cc[4][4], xf[4][4];
#define ZERO4 { _Pragma("unroll") for (int t = 0; t < 4; ++t) \
        { dacc[t][0]=0.f; dacc[t][1]=0.f; dacc[t][2]=0.f; dacc[t][3]=0.f; } }
#define SWAPB() do { __syncthreads(); stB(Bh, Bl, breg, tid); __syncthreads(); } while (0)

    // ---- u ----
    ldB(breg, 7, tid);                      // U_u
    ZERO4; gemm_S<2>(dacc, xH, xL, bH, bL);
    SWAPB();                                // B = U_u
    ldB(breg, 0, tid);                      // W_i
    gemm_S<2>(dacc, suH, suL, bH, bL);
#pragma unroll
    for (int t = 0; t < 4; ++t) {
        float2 b = *(const float2*)(b_u + cbase + t*8);
        cc[t][0]=tanhx(dacc[t][0]+b.x); cc[t][1]=tanhx(dacc[t][1]+b.y);
        cc[t][2]=tanhx(dacc[t][2]+b.x); cc[t][3]=tanhx(dacc[t][3]+b.y);
    }
    // ---- i ----
    SWAPB();                                // B = W_i
    ldB(breg, 4, tid);                      // U_i
    ZERO4; gemm_S<2>(dacc, xH, xL, bH, bL);
    SWAPB();                                // B = U_i
    ldB(breg, 1, tid);                      // W_f
    gemm_S<2>(dacc, suH, suL, bH, bL);
#pragma unroll
    for (int t = 0; t < 4; ++t) {
        float2 b = *(const float2*)(b_i + cbase + t*8);
        cc[t][0]*=sigf(dacc[t][0]+b.x); cc[t][1]*=sigf(dacc[t][1]+b.y);
        cc[t][2]*=sigf(dacc[t][2]+b.x); cc[t][3]*=sigf(dacc[t][3]+b.y);
    }
    // ---- f ----
    SWAPB();                                // B = W_f
    ldB(breg, 5, tid);                      // U_f
    ZERO4; gemm_S<2>(dacc, xH, xL, bH, bL);
#pragma unroll
    for (int t = 0; t < 4; ++t) {
        float2 b = *(const float2*)(b_f + cbase + t*8);
        xf[t][0]=dacc[t][0]+b.x; xf[t][1]=dacc[t][1]+b.y;
        xf[t][2]=dacc[t][2]+b.x; xf[t][3]=dacc[t][3]+b.y;
    }
    SWAPB();                                // B = U_f
    ldB(breg, 2, tid);                      // W_o (early: U_f used twice)
    ZERO4; gemm_S<2>(dacc, s1H, s1L, bH, bL);   // G1 = h1 @ U_f
#pragma unroll
    for (int t = 0; t < 4; ++t) {               // f1 pairs with child1 cell
        int c = cbase + t*8;
        float2 ca = *(const float2*)(g_c + (2*n0+2)*HH + c);
        float2 cbv = *(const float2*)(g_c + (2*n1+2)*HH + c);
        cc[t][0]+=sigf(dacc[t][0]+xf[t][0])*ca.x;
        cc[t][1]+=sigf(dacc[t][1]+xf[t][1])*ca.y;
        cc[t][2]+=sigf(dacc[t][2]+xf[t][2])*cbv.x;
        cc[t][3]+=sigf(dacc[t][3]+xf[t][3])*cbv.y;
        dacc[t][0]=-dacc[t][0]; dacc[t][1]=-dacc[t][1];
        dacc[t][2]=-dacc[t][2]; dacc[t][3]=-dacc[t][3];
    }
    gemm_S<2>(dacc, suH, suL, bH, bL);          // Gsum - G1 = h0 @ U_f
#pragma unroll
    for (int t = 0; t < 4; ++t) {               // f0 pairs with child0 cell
        int c = cbase + t*8;
        float2 ca = *(const float2*)(g_c + (2*n0+1)*HH + c);
        float2 cbv = *(const float2*)(g_c + (2*n1+1)*HH + c);
        cc[t][0]+=sigf(dacc[t][0]+xf[t][0])*ca.x;
        cc[t][1]+=sigf(dacc[t][1]+xf[t][1])*ca.y;
        cc[t][2]+=sigf(dacc[t][2]+xf[t][2])*cbv.x;
        cc[t][3]+=sigf(dacc[t][3]+xf[t][3])*cbv.y;
    }
    // ---- o + store ----
    SWAPB();                                // B = W_o
    ldB(breg, 6, tid);                      // U_o
    ZERO4; gemm_S<2>(dacc, xH, xL, bH, bL);
    SWAPB();                                // B = U_o
    gemm_S<2>(dacc, suH, suL, bH, bL);
#pragma unroll
    for (int t = 0; t < 4; ++t) {
        int c = cbase + t*8;
        float2 b = *(const float2*)(b_o + c);
        float h0 = sigf(dacc[t][0]+b.x)*tanhx(cc[t][0]);
        float h1 = sigf(dacc[t][1]+b.y)*tanhx(cc[t][1]);
        float h2 = sigf(dacc[t][2]+b.x)*tanhx(cc[t][2]);
        float h3 = sigf(dacc[t][3]+b.y)*tanhx(cc[t][3]);
        *(float2*)(g_c + n0*HH + c) = make_float2(cc[t][0], cc[t][1]);
        *(float2*)(g_c + n1*HH + c) = make_float2(cc[t][2], cc[t][3]);
        *(float2*)(g_h + n0*HH + c) = make_float2(h0, h1);
        *(float2*)(g_h + n1*HH + c) = make_float2(h2, h3);
    }
#undef ZERO4
#undef SWAPB
}

// ---------------------------------------------------------------------------
// Small levels (nl < 64): one parent/block, 512 threads, 9 k-split matvecs.
// ---------------------------------------------------------------------------
__global__ void __launch_bounds__(512) small_level_kernel(
    int sl, const float* __restrict__ x,
    const float* __restrict__ W_i, const float* __restrict__ b_i, const float* __restrict__ U_i,
    const float* __restrict__ W_f, const float* __restrict__ b_f, const float* __restrict__ U_f,
    const float* __restrict__ W_o, const float* __restrict__ b_o, const float* __restrict__ U_o,
    const float* __restrict__ W_u, const float* __restrict__ b_u, const float* __restrict__ U_u)
{
    extern __shared__ float smf[];
    float* hs   = smf;              // [h~ | h0 | h1 | x] x 128
    float* part = smf + 512;        // [9][4][128]

    const int t = threadIdx.x;
    const long node = sl + blockIdx.x;
    const long ch0  = 2*node + 1;

    if (t < 128) {
        float h0 = g_h[ch0*HH + t];
        float h1 = g_h[(ch0+1)*HH + t];
        hs[128+t] = h0; hs[256+t] = h1; hs[t] = h0 + h1;
        hs[384+t] = x[node*HH + t];
    }
    __syncthreads();

    const int col = t & 127;
    const int q   = t >> 7;
    const int kb  = q * 32;

#define JOB(J, S, M) { float av = 0.f; const float* s = hs + (S)*128;          \
        _Pragma("unroll 8")                                                    \
        for (int k = 0; k < 32; ++k) av += s[kb+k] * (M)[(kb+k)*HH + col];     \
        part[((J)*4 + q)*128 + col] = av; }
    JOB(0, 0, U_i) JOB(1, 0, U_o) JOB(2, 0, U_u)
    JOB(3, 1, U_f) JOB(4, 2, U_f)
    JOB(5, 3, W_i) JOB(6, 3, W_f) JOB(7, 3, W_o) JOB(8, 3, W_u)
#undef JOB
    __syncthreads();

    if (t < 128) {
#define SUMP(J) (part[((J)*4+0)*128+t] + part[((J)*4+1)*128+t] + \
                 part[((J)*4+2)*128+t] + part[((J)*4+3)*128+t])
        float yi  = SUMP(0), yo = SUMP(1), yu = SUMP(2);
        float yf0 = SUMP(3), yf1 = SUMP(4);
        float xi  = SUMP(5) + b_i[t];
        float xfv = SUMP(6) + b_f[t];
        float xo  = SUMP(7) + b_o[t];
        float xu  = SUMP(8) + b_u[t];
#undef SUMP
        float c = sigf(xi+yi)*tanhx(xu+yu)
                + sigf(xfv+yf0)*g_c[ch0*HH+t] + sigf(xfv+yf1)*g_c[(ch0+1)*HH+t];
        g_c[node*HH+t] = c;
        g_h[node*HH+t] = sigf(xo+yo)*tanhx(c);
    }
}

__global__ void out_kernel(float* __restrict__ out)
{
    int t = threadIdx.x;
    out[t] = (t < 128) ? g_h[t] : g_c[t - 128];
}

// ---------------------------------------------------------------------------
extern "C" void kernel_launch(void* const* d_in, const int* in_sizes, int n_in,
                              void* d_out, int out_size)
{
    const float* x   = (const float*)d_in[0];
    const float* W_i = (const float*)d_in[1];
    const float* b_i = (const float*)d_in[2];
    const float* U_i = (const float*)d_in[3];
    const float* W_f = (const float*)d_in[4];
    const float* b_f = (const float*)d_in[5];
    const float* U_f = (const float*)d_in[6];
    const float* W_o = (const float*)d_in[7];
    const float* b_o = (const float*)d_in[8];
    const float* U_o = (const float*)d_in[9];
    const float* W_u = (const float*)d_in[10];
    const float* b_u = (const float*)d_in[11];
    const float* U_u = (const float*)d_in[12];

    const int SMEM_T = (6*64*PITCH + 2*128*PITCH) * 2;   // 174080
    const int SMEM_L = (4*128*PITCH) * 2;                // 139264
    const int SMEM_S = (512 + 9*4*128) * 4;
    cudaFuncSetAttribute(tlevel_kernel, cudaFuncAttributeMaxDynamicSharedMemorySize, SMEM_T);
    cudaFuncSetAttribute(leaf_kernel,   cudaFuncAttributeMaxDynamicSharedMemorySize, SMEM_L);
    cudaFuncSetAttribute(small_level_kernel, cudaFuncAttributeMaxDynamicSharedMemorySize, SMEM_S);

    conv_w_kernel<<<8, 256>>>(W_i, W_f, W_o, W_u, U_i, U_f, U_o, U_u);

    leaf_kernel<<<(1 << DEPTH) / 128, 512, SMEM_L>>>(x, b_i, b_o, b_u);

    for (int l = DEPTH - 1; l >= 0; --l) {
        int nl = 1 << l;
        int sl = nl - 1;
        if (nl >= 64)
            tlevel_kernel<<<nl / 64, 512, SMEM_T>>>(sl, x, b_i, b_f, b_o, b_u);
        else
            small_level_kernel<<<nl, 512, SMEM_S>>>(sl, x,
                W_i, b_i, U_i, W_f, b_f, U_f, W_o, b_o, U_o, W_u, b_u, U_u);
    }

    out_kernel<<<1, 256>>>((float*)d_out);
}